// round 7
// baseline (speedup 1.0000x reference)
#include <cuda_runtime.h>
#include <cuda_fp16.h>
#include <cstdint>

#define N_NODES 100000
#define E_MAX   1600000
#define D 128

typedef unsigned long long ull;

// Scratch (static device globals: allowed)
__device__ __half g_hh[(size_t)N_NODES * D];        // 25.6 MB: h (fp16)
__device__ int   g_cnt[N_NODES];
__device__ int   g_off[N_NODES + 1];
__device__ int   g_cur[N_NODES];
__device__ int   g_bsum[128];
__device__ ull   g_epack[E_MAX];

__device__ __forceinline__ uint32_t f2tf32(float f) {
    uint32_t r;
    asm("cvt.rna.tf32.f32 %0, %1;" : "=r"(r) : "f"(f));
    return r;
}

// ---------------------------------------------------------------------------
// GEMM via mma.sync tf32: h[N,128] = x[N,128] @ W[128,128]^T, fp16 out.
// CTA: 64x128 tile, K=128 smem-resident -> 101 KB smem -> 2 CTAs/SM.
// 8 warps, each 16x64.
// ---------------------------------------------------------------------------
#define PADK 132   // (132n + j) mod 32 = (4n + j) mod 32 -> conflict-free
#define GEMM_SMEM ((64 + 128) * PADK * 4)

__global__ __launch_bounds__(256) void gemm_mma(const float* __restrict__ x,
                                                const float* __restrict__ W,
                                                int N) {
    extern __shared__ uint32_t smA[];          // As[64][PADK] tf32 bits
    uint32_t* smB = smA + 64 * PADK;           // Bs[128][PADK] = W rows

    const int tid  = threadIdx.x;
    const int row0 = blockIdx.x * 64;

    // A: 64 rows x 32 float4 = 2048 chunks -> 8 per thread
#pragma unroll
    for (int it = 0; it < 8; it++) {
        int idx = it * 256 + tid;
        int r   = idx >> 5;
        int c4  = idx & 31;
        float4 va = make_float4(0.f, 0.f, 0.f, 0.f);
        if (row0 + r < N) va = *(const float4*)(x + (size_t)(row0 + r) * D + c4 * 4);
        uint4 ta = make_uint4(f2tf32(va.x), f2tf32(va.y), f2tf32(va.z), f2tf32(va.w));
        *(uint4*)(smA + r * PADK + c4 * 4) = ta;
    }
    // B: 128 rows x 32 float4 = 4096 chunks -> 16 per thread
#pragma unroll
    for (int it = 0; it < 16; it++) {
        int idx = it * 256 + tid;
        int r   = idx >> 5;
        int c4  = idx & 31;
        float4 vb = *(const float4*)(W + (size_t)r * D + c4 * 4);
        uint4 tb = make_uint4(f2tf32(vb.x), f2tf32(vb.y), f2tf32(vb.z), f2tf32(vb.w));
        *(uint4*)(smB + r * PADK + c4 * 4) = tb;
    }
    __syncthreads();

    const int wid  = tid >> 5, lane = tid & 31;
    const int wm   = (wid >> 1) * 16;     // 0,16,32,48
    const int wn   = (wid & 1) * 64;      // 0,64
    const int gq   = lane >> 2;
    const int tig  = lane & 3;

    float acc[8][4];
#pragma unroll
    for (int nt = 0; nt < 8; nt++)
#pragma unroll
        for (int c = 0; c < 4; c++) acc[nt][c] = 0.f;

#pragma unroll
    for (int k8 = 0; k8 < 16; k8++) {
        const int k = k8 * 8;
        uint32_t a0 = smA[(wm + gq)     * PADK + k + tig];
        uint32_t a1 = smA[(wm + 8 + gq) * PADK + k + tig];
        uint32_t a2 = smA[(wm + gq)     * PADK + k + 4 + tig];
        uint32_t a3 = smA[(wm + 8 + gq) * PADK + k + 4 + tig];
        uint32_t b[8][2];
#pragma unroll
        for (int nt = 0; nt < 8; nt++) {
            int n = wn + nt * 8 + gq;
            b[nt][0] = smB[n * PADK + k + tig];
            b[nt][1] = smB[n * PADK + k + 4 + tig];
        }
#pragma unroll
        for (int nt = 0; nt < 8; nt++) {
            asm volatile(
                "mma.sync.aligned.m16n8k8.row.col.f32.tf32.tf32.f32 "
                "{%0,%1,%2,%3}, {%4,%5,%6,%7}, {%8,%9}, {%0,%1,%2,%3};"
                : "+f"(acc[nt][0]), "+f"(acc[nt][1]),
                  "+f"(acc[nt][2]), "+f"(acc[nt][3])
                : "r"(a0), "r"(a1), "r"(a2), "r"(a3),
                  "r"(b[nt][0]), "r"(b[nt][1]));
        }
    }

    int r1 = row0 + wm + gq;
    int r2 = r1 + 8;
#pragma unroll
    for (int nt = 0; nt < 8; nt++) {
        int c = wn + nt * 8 + tig * 2;
        if (r1 < N)
            *(__half2*)(g_hh + (size_t)r1 * D + c) = __floats2half2_rn(acc[nt][0], acc[nt][1]);
        if (r2 < N)
            *(__half2*)(g_hh + (size_t)r2 * D + c) = __floats2half2_rn(acc[nt][2], acc[nt][3]);
    }
}

// ---------------------------------------------------------------------------
// CSR build — 4 edges/thread for MLP
// ---------------------------------------------------------------------------
__global__ void k_hist(const int* __restrict__ ei, int E) {
    int i = (blockIdx.x * blockDim.x + threadIdx.x) * 4;
    if (i + 3 < E && (E & 3) == 0) {
        int4 d = __ldg((const int4*)(ei + E + i));
        atomicAdd(&g_cnt[d.x], 1);
        atomicAdd(&g_cnt[d.y], 1);
        atomicAdd(&g_cnt[d.z], 1);
        atomicAdd(&g_cnt[d.w], 1);
    } else {
        for (int e = i; e < E && e < i + 4; e++)
            atomicAdd(&g_cnt[__ldg(ei + E + e)], 1);
    }
}

__global__ __launch_bounds__(1024) void k_scan1(int N) {
    __shared__ int wsum[32];
    int t = threadIdx.x;
    int i = blockIdx.x * 1024 + t;
    int lane = t & 31, wid = t >> 5;
    int v = (i < N) ? g_cnt[i] : 0;
    int x = v;
#pragma unroll
    for (int o = 1; o < 32; o <<= 1) {
        int y = __shfl_up_sync(0xffffffffu, x, o);
        if (lane >= o) x += y;
    }
    if (lane == 31) wsum[wid] = x;
    __syncthreads();
    if (wid == 0) {
        int s = wsum[lane];
#pragma unroll
        for (int o = 1; o < 32; o <<= 1) {
            int y = __shfl_up_sync(0xffffffffu, s, o);
            if (lane >= o) s += y;
        }
        wsum[lane] = s;
    }
    __syncthreads();
    int pre = (wid > 0) ? wsum[wid - 1] : 0;
    if (i < N) g_off[i] = pre + x - v;
    if (t == 1023) g_bsum[blockIdx.x] = pre + x;
}

__global__ __launch_bounds__(256) void k_scan23(int N, int nb, int E) {
    __shared__ int s[128];
    int t = threadIdx.x;
    if (t < 128) s[t] = (t < nb) ? g_bsum[t] : 0;
    __syncthreads();
#pragma unroll
    for (int o = 1; o < 128; o <<= 1) {
        int add = (t < 128 && t >= o) ? s[t - o] : 0;
        __syncthreads();
        if (t < 128) s[t] += add;
        __syncthreads();
    }
    int i = blockIdx.x * 256 + t;
    if (i < N) {
        int blk = i >> 10;
        int o = g_off[i] + (blk > 0 ? s[blk - 1] : 0);
        g_off[i] = o;
        g_cur[i] = o;
    }
    if (i == 0) g_off[N_NODES] = E;
}

__global__ void k_fill(const int* __restrict__ ei, const float* __restrict__ ew, int E) {
    int i = (blockIdx.x * blockDim.x + threadIdx.x) * 4;
    if (i + 3 < E && (E & 3) == 0) {
        int4   s4 = __ldg((const int4*)(ei + i));
        int4   d4 = __ldg((const int4*)(ei + E + i));
        float4 w4 = __ldg((const float4*)(ew + i));
        int p0 = atomicAdd(&g_cur[d4.x], 1);
        int p1 = atomicAdd(&g_cur[d4.y], 1);
        int p2 = atomicAdd(&g_cur[d4.z], 1);
        int p3 = atomicAdd(&g_cur[d4.w], 1);
        g_epack[p0] = ((ull)(unsigned)s4.x << 32) | (ull)__float_as_uint(w4.x);
        g_epack[p1] = ((ull)(unsigned)s4.y << 32) | (ull)__float_as_uint(w4.y);
        g_epack[p2] = ((ull)(unsigned)s4.z << 32) | (ull)__float_as_uint(w4.z);
        g_epack[p3] = ((ull)(unsigned)s4.w << 32) | (ull)__float_as_uint(w4.w);
    } else {
        for (int e = i; e < E && e < i + 4; e++) {
            int src = __ldg(ei + e);
            int dst = __ldg(ei + E + e);
            int pos = atomicAdd(&g_cur[dst], 1);
            g_epack[pos] = ((ull)(unsigned)src << 32) | (ull)__float_as_uint(__ldg(ew + e));
        }
    }
}

// ---------------------------------------------------------------------------
// Gather (fp16 h) + fused epilogue: warp per dst, 4-way unroll.
// ---------------------------------------------------------------------------
__global__ __launch_bounds__(256) void gather_csr(const float* __restrict__ bias,
                                                  const float* __restrict__ pa,
                                                  float* __restrict__ out, int N) {
    int d    = (blockIdx.x * blockDim.x + threadIdx.x) >> 5;
    int lane = threadIdx.x & 31;
    if (d >= N) return;

    int beg = g_off[d];
    int end = g_off[d + 1];

    float4 a0 = make_float4(0.f, 0.f, 0.f, 0.f);
    float4 a1 = make_float4(0.f, 0.f, 0.f, 0.f);
    float4 a2 = make_float4(0.f, 0.f, 0.f, 0.f);
    float4 a3 = make_float4(0.f, 0.f, 0.f, 0.f);

    const __half* hp = g_hh;
    int i = beg;
    for (; i + 3 < end; i += 4) {
        ull p0 = __ldg(g_epack + i);
        ull p1 = __ldg(g_epack + i + 1);
        ull p2 = __ldg(g_epack + i + 2);
        ull p3 = __ldg(g_epack + i + 3);
        uint2 u0 = __ldg((const uint2*)(hp + (size_t)(p0 >> 32) * D + lane * 4));
        uint2 u1 = __ldg((const uint2*)(hp + (size_t)(p1 >> 32) * D + lane * 4));
        uint2 u2 = __ldg((const uint2*)(hp + (size_t)(p2 >> 32) * D + lane * 4));
        uint2 u3 = __ldg((const uint2*)(hp + (size_t)(p3 >> 32) * D + lane * 4));
        float w0 = __uint_as_float((unsigned)p0);
        float w1 = __uint_as_float((unsigned)p1);
        float w2 = __uint_as_float((unsigned)p2);
        float w3 = __uint_as_float((unsigned)p3);
        {
            float2 f0 = __half22float2(*(__half2*)&u0.x);
            float2 f1 = __half22float2(*(__half2*)&u0.y);
            a0.x += w0 * f0.x; a0.y += w0 * f0.y; a0.z += w0 * f1.x; a0.w += w0 * f1.y;
        }
        {
            float2 f0 = __half22float2(*(__half2*)&u1.x);
            float2 f1 = __half22float2(*(__half2*)&u1.y);
            a1.x += w1 * f0.x; a1.y += w1 * f0.y; a1.z += w1 * f1.x; a1.w += w1 * f1.y;
        }
        {
            float2 f0 = __half22float2(*(__half2*)&u2.x);
            float2 f1 = __half22float2(*(__half2*)&u2.y);
            a2.x += w2 * f0.x; a2.y += w2 * f0.y; a2.z += w2 * f1.x; a2.w += w2 * f1.y;
        }
        {
            float2 f0 = __half22float2(*(__half2*)&u3.x);
            float2 f1 = __half22float2(*(__half2*)&u3.y);
            a3.x += w3 * f0.x; a3.y += w3 * f0.y; a3.z += w3 * f1.x; a3.w += w3 * f1.y;
        }
    }
    for (; i < end; i++) {
        ull p0 = __ldg(g_epack + i);
        float w0 = __uint_as_float((unsigned)p0);
        uint2 u0 = __ldg((const uint2*)(hp + (size_t)(p0 >> 32) * D + lane * 4));
        float2 f0 = __half22float2(*(__half2*)&u0.x);
        float2 f1 = __half22float2(*(__half2*)&u0.y);
        a0.x += w0 * f0.x; a0.y += w0 * f0.y; a0.z += w0 * f1.x; a0.w += w0 * f1.y;
    }

    float  a = pa[0];
    float4 b = *(const float4*)(bias + lane * 4);
    float4 v;
    v.x = a0.x + a1.x + a2.x + a3.x + b.x;
    v.y = a0.y + a1.y + a2.y + a3.y + b.y;
    v.z = a0.z + a1.z + a2.z + a3.z + b.z;
    v.w = a0.w + a1.w + a2.w + a3.w + b.w;
    v.x = fmaxf(v.x >= 0.f ? v.x : a * v.x, 0.f);
    v.y = fmaxf(v.y >= 0.f ? v.y : a * v.y, 0.f);
    v.z = fmaxf(v.z >= 0.f ? v.z : a * v.z, 0.f);
    v.w = fmaxf(v.w >= 0.f ? v.w : a * v.w, 0.f);
    *(float4*)(out + (size_t)d * D + lane * 4) = v;
}

// ---------------------------------------------------------------------------
extern "C" void kernel_launch(void* const* d_in, const int* in_sizes, int n_in,
                              void* d_out, int out_size) {
    const float* x    = (const float*)d_in[0];
    const int*   ei   = (const int*)  d_in[1];
    const float* ew   = (const float*)d_in[2];
    const float* W    = (const float*)d_in[3];
    const float* bias = (const float*)d_in[4];
    const float* pa   = (const float*)d_in[5];
    float*       out  = (float*)d_out;

    const int N = in_sizes[0] / D;      // 100000
    const int E = in_sizes[2];          // 1600000
    const int nb = (N + 1023) / 1024;   // 98
    const int e4 = (E + 3) / 4;

    // zero histogram (memset node, no kernel)
    void* cnt_ptr = nullptr;
    cudaGetSymbolAddress(&cnt_ptr, g_cnt);
    cudaMemsetAsync(cnt_ptr, 0, (size_t)N * sizeof(int));

    // CSR build
    k_hist<<<(e4 + 255) / 256, 256>>>(ei, E);
    k_scan1<<<nb, 1024>>>(N);
    k_scan23<<<(N + 255) / 256, 256>>>(N, nb, E);
    k_fill<<<(e4 + 255) / 256, 256>>>(ei, ew, E);

    // h = x @ W^T on tensor cores (mma.sync tf32), fp16 output
    cudaFuncSetAttribute(gemm_mma, cudaFuncAttributeMaxDynamicSharedMemorySize, GEMM_SMEM);
    gemm_mma<<<(N + 63) / 64, 256, GEMM_SMEM>>>(x, W, N);

    // gather + bias + prelu + relu
    gather_csr<<<(N * 32 + 255) / 256, 256>>>(bias, pa, out, N);
}